// round 4
// baseline (speedup 1.0000x reference)
#include <cuda_runtime.h>
#include <cstdint>

// ----------------------------------------------------------------------------
// BlockLinear via mma.sync tf32 (compute_103: no tcgen05).
// out[4096, 64*256] = x-blocks @ w-blocks^T + bias
// CTA: M=128 x N=256 tile, K=256 in 8 chunks of 32.
// Data path: cp.async -> raw smem -> repack (LDS.128 + cvt.rna.tf32 + STS.64,
// fragment-pair layout, conflict-free) -> inner loop of LDS.64 + HMMA only.
// 512 threads = 16 warps (2m x 8n), warp tile 64x32, mma m16n8k8.
// ----------------------------------------------------------------------------

#define NBLK    64
#define INB     256
#define OUTB    256
#define BATCHSZ 4096
#define ROWF    (NBLK * INB)    // 16384

#define MT      128
#define NT      256
#define KC      32
#define NCHUNK  (INB / KC)      // 8
#define NRAW    3               // raw cp.async stages

#define RAWPITCH   36                          // floats per raw row (144B)
#define A_RAW      (MT * RAWPITCH * 4)         // 18432
#define B_RAW      (NT * RAWPITCH * 4)         // 36864
#define RAW_STAGE  (A_RAW + B_RAW)             // 55296

// fragment-pair planes (uint2 units), odd stride => conflict-free STS/LDS.64
#define FA_PLANE   513          // >= 128*4
#define FB_PLANE   1025         // >= 256*4

#define SM_BIAS   0
#define SM_FRAGA  1024
#define SM_FRAGB  (SM_FRAGA + 4 * FA_PLANE * 8)          // 1024 + 16416 = 17440
#define SM_RAW    (SM_FRAGB + 4 * FB_PLANE * 8)          // 17440 + 32800 = 50240
#define SMEM_TOTAL (SM_RAW + NRAW * RAW_STAGE)           // 216128

// ---------------- device helpers ----------------

__device__ __forceinline__ uint32_t smem_u32(const void* p) {
    uint32_t a;
    asm("{ .reg .u64 t; cvta.to.shared.u64 t, %1; cvt.u32.u64 %0, t; }" : "=r"(a) : "l"(p));
    return a;
}

__device__ __forceinline__ void cp16(uint32_t dst, const void* src) {
    asm volatile("cp.async.cg.shared.global [%0], [%1], 16;" :: "r"(dst), "l"(src));
}

__device__ __forceinline__ uint32_t f2tf32(float f) {
    uint32_t r;
    asm("cvt.rna.tf32.f32 %0, %1;" : "=r"(r) : "f"(f));
    return r;
}

__device__ __forceinline__ void lds128(float* v, uint32_t addr) {
    asm volatile("ld.shared.v4.f32 {%0,%1,%2,%3}, [%4];"
                 : "=f"(v[0]), "=f"(v[1]), "=f"(v[2]), "=f"(v[3]) : "r"(addr));
}

__device__ __forceinline__ void sts64(uint32_t addr, uint32_t lo, uint32_t hi) {
    asm volatile("st.shared.v2.b32 [%0], {%1,%2};" :: "r"(addr), "r"(lo), "r"(hi));
}

__device__ __forceinline__ void lds64(uint32_t& lo, uint32_t& hi, uint32_t addr) {
    asm volatile("ld.shared.v2.b32 {%0,%1}, [%2];" : "=r"(lo), "=r"(hi) : "r"(addr));
}

__device__ __forceinline__ void mma_tf32(float* c, const uint32_t* a, const uint32_t* b) {
    asm volatile(
        "mma.sync.aligned.m16n8k8.row.col.f32.tf32.tf32.f32 "
        "{%0,%1,%2,%3}, {%4,%5,%6,%7}, {%8,%9}, {%0,%1,%2,%3};"
        : "+f"(c[0]), "+f"(c[1]), "+f"(c[2]), "+f"(c[3])
        : "r"(a[0]), "r"(a[1]), "r"(a[2]), "r"(a[3]), "r"(b[0]), "r"(b[1]));
}

// ---------------- kernel ----------------

__global__ void __launch_bounds__(512, 1)
blocklinear_mma_kernel(const float* __restrict__ x,
                       const float* __restrict__ w,
                       const float* __restrict__ bias,
                       float* __restrict__ out) {
    extern __shared__ char smem[];
    const uint32_t sbase = smem_u32(smem);
    const int tid   = threadIdx.x;
    const int blk   = blockIdx.x;   // 0..63  weight block
    const int mtile = blockIdx.y;   // 0..31  batch slice

    if (tid < NT)
        reinterpret_cast<float*>(smem + SM_BIAS)[tid] = bias[blk * OUTB + tid];

    const int wid  = tid >> 5;
    const int lane = tid & 31;
    const int gID  = lane >> 2;
    const int tig  = lane & 3;
    const int wm   = wid >> 3;      // 0..1  -> 64-row strip
    const int wn   = wid & 7;       // 0..7  -> 32-col strip

    // ---- cp.async stage loader (gmem -> raw smem, pitch 36 floats) ----
    auto cp_stage = [&](int kc, int s) {
        const uint32_t rA = sbase + SM_RAW + s * RAW_STAGE;
        const uint32_t rB = rA + A_RAW;
        const int kcol = kc * KC;
#pragma unroll
        for (int it = 0; it < 2; it++) {                 // A: 1024 16B chunks
            int id = tid + it * 512;
            int row = id >> 3, c4 = id & 7;
            const float* g = x + (size_t)(mtile * MT + row) * ROWF
                               + blk * INB + kcol + c4 * 4;
            cp16(rA + row * (RAWPITCH * 4) + c4 * 16, g);
        }
#pragma unroll
        for (int it = 0; it < 4; it++) {                 // B: 2048 16B chunks
            int id = tid + it * 512;
            int row = id >> 3, c4 = id & 7;
            const float* g = w + ((size_t)blk * OUTB + row) * INB + kcol + c4 * 4;
            cp16(rB + row * (RAWPITCH * 4) + c4 * 16, g);
        }
    };

#pragma unroll
    for (int s = 0; s < NRAW; s++) {
        cp_stage(s, s);
        asm volatile("cp.async.commit_group;" ::: "memory");
    }

    float acc[4][4][4];
#pragma unroll
    for (int i = 0; i < 4; i++)
#pragma unroll
        for (int j = 0; j < 4; j++)
#pragma unroll
            for (int r = 0; r < 4; r++) acc[i][j][r] = 0.0f;

    // precomputed fragment smem addresses (bytes)
    const uint32_t faBase = sbase + SM_FRAGA + (((wm * 64 + gID) * 4 + tig) << 3);
    const uint32_t fbBase = sbase + SM_FRAGB + (((wn * 32 + gID) * 4 + tig) << 3);

    for (int kc = 0; kc < NCHUNK; kc++) {
        asm volatile("cp.async.wait_group %0;" :: "n"(NRAW - 1) : "memory");
        __syncthreads();   // raw[kc%NRAW] ready; frag free (compute kc-1 done)

        const int s = kc % NRAW;
        const uint32_t rA = sbase + SM_RAW + s * RAW_STAGE;
        const uint32_t rB = rA + A_RAW;

        // ---- repack raw -> fragment-pair layout (cvt once per element) ----
        {
            // A: 512 units (row, ks) -> 1 per thread
            int row = tid >> 2, ks = tid & 3;
            float v[8];
            lds128(v + 0, rA + row * (RAWPITCH * 4) + ks * 32);
            lds128(v + 4, rA + row * (RAWPITCH * 4) + ks * 32 + 16);
            uint32_t dst = sbase + SM_FRAGA + ((ks * FA_PLANE + row * 4) << 3);
#pragma unroll
            for (int t = 0; t < 4; t++)
                sts64(dst + (t << 3), f2tf32(v[t]), f2tf32(v[t + 4]));
            // B: 1024 units -> 2 per thread
#pragma unroll
            for (int it = 0; it < 2; it++) {
                int u = tid + it * 512;
                int col = u >> 2, ks2 = u & 3;
                float vb[8];
                lds128(vb + 0, rB + col * (RAWPITCH * 4) + ks2 * 32);
                lds128(vb + 4, rB + col * (RAWPITCH * 4) + ks2 * 32 + 16);
                uint32_t db = sbase + SM_FRAGB + ((ks2 * FB_PLANE + col * 4) << 3);
#pragma unroll
                for (int t = 0; t < 4; t++)
                    sts64(db + (t << 3), f2tf32(vb[t]), f2tf32(vb[t + 4]));
            }
        }
        __syncthreads();

        // refill the raw slot just consumed (slot s free after repack)
        if (kc + NRAW < NCHUNK) cp_stage(kc + NRAW, s);
        asm volatile("cp.async.commit_group;" ::: "memory");  // unconditional: keeps group count uniform

        // ---- compute: pure LDS.64 + HMMA ----
#pragma unroll
        for (int ks = 0; ks < 4; ks++) {
            const uint32_t fa = faBase + ((ks * FA_PLANE) << 3);
            const uint32_t fb = fbBase + ((ks * FB_PLANE) << 3);
            uint32_t a[4][4], b[4][2];
#pragma unroll
            for (int i = 0; i < 4; i++) {
                lds64(a[i][0], a[i][2], fa + ((i * 64) << 3));        // row gID
                lds64(a[i][1], a[i][3], fa + ((i * 64 + 32) << 3));   // row gID+8
            }
#pragma unroll
            for (int j = 0; j < 4; j++)
                lds64(b[j][0], b[j][1], fb + ((j * 32) << 3));
#pragma unroll
            for (int i = 0; i < 4; i++)
#pragma unroll
                for (int j = 0; j < 4; j++)
                    mma_tf32(acc[i][j], a[i], b[j]);
        }
    }

    // ---- epilogue: bias + store ----
    const float* bsm = reinterpret_cast<const float*>(smem + SM_BIAS);
#pragma unroll
    for (int i = 0; i < 4; i++) {
        const int row0 = mtile * MT + wm * 64 + i * 16 + gID;
#pragma unroll
        for (int j = 0; j < 4; j++) {
            const int colL = wn * 32 + j * 8 + tig * 2;
            const int colG = blk * OUTB + colL;
            float2 v0, v1;
            v0.x = acc[i][j][0] + bsm[colL];
            v0.y = acc[i][j][1] + bsm[colL + 1];
            v1.x = acc[i][j][2] + bsm[colL];
            v1.y = acc[i][j][3] + bsm[colL + 1];
            *reinterpret_cast<float2*>(out + (size_t)row0 * ROWF + colG) = v0;
            *reinterpret_cast<float2*>(out + (size_t)(row0 + 8) * ROWF + colG) = v1;
        }
    }
}

// ---------------- host ----------------

extern "C" void kernel_launch(void* const* d_in, const int* in_sizes, int n_in,
                              void* d_out, int out_size) {
    const float* x    = (const float*)d_in[0];
    const float* w    = (const float*)d_in[1];
    const float* bias = (const float*)d_in[2];
    float* out        = (float*)d_out;

    static bool attr_done = false;
    if (!attr_done) {
        cudaFuncSetAttribute(blocklinear_mma_kernel,
                             cudaFuncAttributeMaxDynamicSharedMemorySize, SMEM_TOTAL);
        attr_done = true;
    }

    dim3 grid(NBLK, BATCHSZ / MT);   // (64, 32)
    blocklinear_mma_kernel<<<grid, 512, SMEM_TOTAL>>>(x, w, bias, out);
}

// round 8
// speedup vs baseline: 1.7646x; 1.7646x over previous
#include <cuda_runtime.h>
#include <cstdint>

// ----------------------------------------------------------------------------
// BlockLinear via mma.sync tf32 (compute_103: no tcgen05).
// out[4096, 64*256] = x-blocks @ w-blocks^T + bias
// R5: occupancy-driven re-tile. CTA = 64x256 tile, 256 threads (8 warps,
// warp tile 64x32), 2-stage cp.async double buffer -> 2 CTAs/SM (8 warps/SMSP).
// Inner loop identical to R3 (direct LDS + cvt.rna.tf32 + m16n8k8 HMMA).
// ----------------------------------------------------------------------------

#define NBLK    64
#define INB     256
#define OUTB    256
#define BATCHSZ 4096
#define ROWF    (NBLK * INB)    // 16384

#define MT      64
#define NT      256
#define KC      32
#define NCHUNK  (INB / KC)      // 8
#define NSTAGE  2

#define PADF    36                        // floats per smem row (144B): conflict-free
#define A_BYTES (MT * PADF * 4)           // 9216
#define B_BYTES (NT * PADF * 4)           // 36864
#define STAGE_BYTES (A_BYTES + B_BYTES)   // 46080
#define SM_BIAS  0
#define SM_TILES 1024
#define SMEM_TOTAL (SM_TILES + NSTAGE * STAGE_BYTES)   // 93184 -> 2 CTAs/SM

// ---------------- device helpers ----------------

__device__ __forceinline__ uint32_t smem_u32(const void* p) {
    uint32_t a;
    asm("{ .reg .u64 t; cvta.to.shared.u64 t, %1; cvt.u32.u64 %0, t; }" : "=r"(a) : "l"(p));
    return a;
}

__device__ __forceinline__ void cp16(uint32_t dst, const void* src) {
    asm volatile("cp.async.cg.shared.global [%0], [%1], 16;" :: "r"(dst), "l"(src));
}

__device__ __forceinline__ uint32_t f2tf32(float f) {
    uint32_t r;
    asm("cvt.rna.tf32.f32 %0, %1;" : "=r"(r) : "f"(f));
    return r;
}

__device__ __forceinline__ void mma_tf32(float* c, const uint32_t* a, const uint32_t* b) {
    asm volatile(
        "mma.sync.aligned.m16n8k8.row.col.f32.tf32.tf32.f32 "
        "{%0,%1,%2,%3}, {%4,%5,%6,%7}, {%8,%9}, {%0,%1,%2,%3};"
        : "+f"(c[0]), "+f"(c[1]), "+f"(c[2]), "+f"(c[3])
        : "r"(a[0]), "r"(a[1]), "r"(a[2]), "r"(a[3]), "r"(b[0]), "r"(b[1]));
}

// ---------------- kernel ----------------

__global__ void __launch_bounds__(256, 2)
blocklinear_mma_kernel(const float* __restrict__ x,
                       const float* __restrict__ w,
                       const float* __restrict__ bias,
                       float* __restrict__ out) {
    extern __shared__ char smem[];
    const uint32_t sbase = smem_u32(smem);
    const int tid   = threadIdx.x;
    const int blk   = blockIdx.x;   // 0..63  weight block (fast dim: w L2 reuse)
    const int mtile = blockIdx.y;   // 0..63  64-row batch slice

    reinterpret_cast<float*>(smem + SM_BIAS)[tid] = bias[blk * OUTB + tid];

    const int wid  = tid >> 5;      // 0..7  -> 32-col strip
    const int lane = tid & 31;
    const int gID  = lane >> 2;
    const int tig  = lane & 3;

    // ---- cp.async stage loader: A [64 x 32] + B [256 x 32], 16B chunks ----
    auto cp_stage = [&](int kc, int s) {
        const uint32_t sA = sbase + SM_TILES + s * STAGE_BYTES;
        const uint32_t sB = sA + A_BYTES;
        const int kcol = kc * KC;
#pragma unroll
        for (int it = 0; it < 2; it++) {                 // A: 512 chunks / 256 thr
            int id = tid + it * 256;
            int row = id >> 3, c4 = id & 7;
            const float* g = x + (size_t)(mtile * MT + row) * ROWF
                               + blk * INB + kcol + c4 * 4;
            cp16(sA + row * (PADF * 4) + c4 * 16, g);
        }
#pragma unroll
        for (int it = 0; it < 8; it++) {                 // B: 2048 chunks / 256 thr
            int id = tid + it * 256;
            int row = id >> 3, c4 = id & 7;
            const float* g = w + ((size_t)blk * OUTB + row) * INB + kcol + c4 * 4;
            cp16(sB + row * (PADF * 4) + c4 * 16, g);
        }
    };

    // prologue: fill both stages
#pragma unroll
    for (int s = 0; s < NSTAGE; s++) {
        cp_stage(s, s);
        asm volatile("cp.async.commit_group;" ::: "memory");
    }

    float acc[4][4][4];
#pragma unroll
    for (int i = 0; i < 4; i++)
#pragma unroll
        for (int j = 0; j < 4; j++)
#pragma unroll
            for (int r = 0; r < 4; r++) acc[i][j][r] = 0.0f;

    for (int kc = 0; kc < NCHUNK; kc++) {
        asm volatile("cp.async.wait_group %0;" :: "n"(NSTAGE - 1) : "memory");
        __syncthreads();   // stage kc%2 ready

        const int s = kc & 1;
        const float* As = reinterpret_cast<const float*>(smem + SM_TILES + s * STAGE_BYTES);
        const float* Bs = reinterpret_cast<const float*>(smem + SM_TILES + s * STAGE_BYTES + A_BYTES);

        // ---- compute: LDS + cvt + HMMA (R3-proven mapping, wm==0) ----
#pragma unroll
        for (int ks = 0; ks < KC / 8; ks++) {
            const int kk = ks * 8 + tig;
            uint32_t a[4][4], b[4][2];
#pragma unroll
            for (int i = 0; i < 4; i++) {
                int r0 = i * 16 + gID;
                a[i][0] = f2tf32(As[r0 * PADF + kk]);
                a[i][1] = f2tf32(As[(r0 + 8) * PADF + kk]);
                a[i][2] = f2tf32(As[r0 * PADF + kk + 4]);
                a[i][3] = f2tf32(As[(r0 + 8) * PADF + kk + 4]);
            }
#pragma unroll
            for (int j = 0; j < 4; j++) {
                int n0 = wid * 32 + j * 8 + gID;
                b[j][0] = f2tf32(Bs[n0 * PADF + kk]);
                b[j][1] = f2tf32(Bs[n0 * PADF + kk + 4]);
            }
#pragma unroll
            for (int i = 0; i < 4; i++)
#pragma unroll
                for (int j = 0; j < 4; j++)
                    mma_tf32(acc[i][j], a[i], b[j]);
        }

        __syncthreads();   // all warps done reading stage s before refill

        // refill the consumed slot (in flight during compute of stage s^1)
        if (kc + NSTAGE < NCHUNK) cp_stage(kc + NSTAGE, s);
        asm volatile("cp.async.commit_group;" ::: "memory");  // uniform group count
    }

    // ---- epilogue: bias + store (float2) ----
    const float* bsm = reinterpret_cast<const float*>(smem + SM_BIAS);
#pragma unroll
    for (int i = 0; i < 4; i++) {
        const int row0 = mtile * MT + i * 16 + gID;
#pragma unroll
        for (int j = 0; j < 4; j++) {
            const int colL = wid * 32 + j * 8 + tig * 2;
            const int colG = blk * OUTB + colL;
            float2 v0, v1;
            v0.x = acc[i][j][0] + bsm[colL];
            v0.y = acc[i][j][1] + bsm[colL + 1];
            v1.x = acc[i][j][2] + bsm[colL];
            v1.y = acc[i][j][3] + bsm[colL + 1];
            *reinterpret_cast<float2*>(out + (size_t)row0 * ROWF + colG) = v0;
            *reinterpret_cast<float2*>(out + (size_t)(row0 + 8) * ROWF + colG) = v1;
        }
    }
}

// ---------------- host ----------------

extern "C" void kernel_launch(void* const* d_in, const int* in_sizes, int n_in,
                              void* d_out, int out_size) {
    const float* x    = (const float*)d_in[0];
    const float* w    = (const float*)d_in[1];
    const float* bias = (const float*)d_in[2];
    float* out        = (float*)d_out;

    static bool attr_done = false;
    if (!attr_done) {
        cudaFuncSetAttribute(blocklinear_mma_kernel,
                             cudaFuncAttributeMaxDynamicSharedMemorySize, SMEM_TOTAL);
        attr_done = true;
    }

    dim3 grid(NBLK, BATCHSZ / MT);   // (64, 64): blk fast -> w reuse within wave
    blocklinear_mma_kernel<<<grid, 256, SMEM_TOTAL>>>(x, w, bias, out);
}

// round 11
// speedup vs baseline: 1.9666x; 1.1145x over previous
#include <cuda_runtime.h>
#include <cstdint>

// ----------------------------------------------------------------------------
// BlockLinear via mma.sync tf32 + ldmatrix (compute_103: no tcgen05).
// out[4096, 64*256] = x-blocks @ w-blocks^T + bias
// R9/R11: ldmatrix-on-tf32. w pre-rounded to tf32 (rna) by a prologue kernel
// into a __device__ array; x fed raw (HW tf32 truncation). Fragments loaded
// with ldmatrix.m8n8.x4.b16 (moves 32-bit tf32 as b16 pairs) -> inner loop is
// 6 ldmatrix + 16 HMMA per k8-slice. CTA 64x256, 256 thr, 2-stage, 2 CTAs/SM.
// ----------------------------------------------------------------------------

#define NBLK    64
#define INB     256
#define OUTB    256
#define BATCHSZ 4096
#define ROWF    (NBLK * INB)    // 16384
#define WELEMS  (NBLK * OUTB * INB)   // 4194304

#define MT      64
#define NT      256
#define KC      32
#define NCHUNK  (INB / KC)      // 8
#define NSTAGE  2

#define PADF    36                        // floats per smem row (144B)
#define A_BYTES (MT * PADF * 4)           // 9216
#define B_BYTES (NT * PADF * 4)           // 36864
#define STAGE_BYTES (A_BYTES + B_BYTES)   // 46080
#define SM_BIAS  0
#define SM_TILES 1024
#define SMEM_TOTAL (SM_TILES + NSTAGE * STAGE_BYTES)   // 93184 -> 2 CTAs/SM

// pre-rounded tf32 weights (static device scratch: allowed; no allocation)
__device__ float g_wtf32[WELEMS];

// ---------------- device helpers ----------------

__device__ __forceinline__ uint32_t smem_u32(const void* p) {
    uint32_t a;
    asm("{ .reg .u64 t; cvta.to.shared.u64 t, %1; cvt.u32.u64 %0, t; }" : "=r"(a) : "l"(p));
    return a;
}

__device__ __forceinline__ void cp16(uint32_t dst, const void* src) {
    asm volatile("cp.async.cg.shared.global [%0], [%1], 16;" :: "r"(dst), "l"(src));
}

__device__ __forceinline__ uint32_t f2tf32(float f) {
    uint32_t r;
    asm("cvt.rna.tf32.f32 %0, %1;" : "=r"(r) : "f"(f));
    return r;
}

// ldmatrix x4 b16: moves 4 tiles of 8 rows x 16B; per-lane address = row start.
__device__ __forceinline__ void ldsm4(uint32_t* r, uint32_t addr) {
    asm volatile("ldmatrix.sync.aligned.m8n8.x4.shared.b16 {%0,%1,%2,%3}, [%4];"
                 : "=r"(r[0]), "=r"(r[1]), "=r"(r[2]), "=r"(r[3]) : "r"(addr));
}

__device__ __forceinline__ void mma_tf32(float* c, const uint32_t* a, const uint32_t* b) {
    asm volatile(
        "mma.sync.aligned.m16n8k8.row.col.f32.tf32.tf32.f32 "
        "{%0,%1,%2,%3}, {%4,%5,%6,%7}, {%8,%9}, {%0,%1,%2,%3};"
        : "+f"(c[0]), "+f"(c[1]), "+f"(c[2]), "+f"(c[3])
        : "r"(a[0]), "r"(a[1]), "r"(a[2]), "r"(a[3]), "r"(b[0]), "r"(b[1]));
}

// ---------------- prologue: round w to tf32 (rna) ----------------

__global__ void __launch_bounds__(256)
round_w_kernel(const float4* __restrict__ w) {
    int i = blockIdx.x * blockDim.x + threadIdx.x;       // over float4s
    float4 v = w[i];
    float4 o;
    o.x = __uint_as_float(f2tf32(v.x));
    o.y = __uint_as_float(f2tf32(v.y));
    o.z = __uint_as_float(f2tf32(v.z));
    o.w = __uint_as_float(f2tf32(v.w));
    reinterpret_cast<float4*>(g_wtf32)[i] = o;
}

// ---------------- main kernel ----------------

__global__ void __launch_bounds__(256, 2)
blocklinear_mma_kernel(const float* __restrict__ x,
                       const float* __restrict__ bias,
                       float* __restrict__ out) {
    extern __shared__ char smem[];
    const uint32_t sbase = smem_u32(smem);
    const int tid   = threadIdx.x;
    const int blk   = blockIdx.x;   // 0..63  weight block (fast dim: w reuse)
    const int mtile = blockIdx.y;   // 0..63  64-row batch slice

    reinterpret_cast<float*>(smem + SM_BIAS)[tid] = bias[blk * OUTB + tid];

    const int wid  = tid >> 5;      // 0..7 -> 32-col strip
    const int lane = tid & 31;
    const int gID  = lane >> 2;
    const int tig  = lane & 3;

    // ---- cp.async stage loader: A [64x32] from x, B [256x32] from g_wtf32 ----
    auto cp_stage = [&](int kc, int s) {
        const uint32_t sA = sbase + SM_TILES + s * STAGE_BYTES;
        const uint32_t sB = sA + A_BYTES;
        const int kcol = kc * KC;
#pragma unroll
        for (int it = 0; it < 2; it++) {                 // A: 512 16B chunks
            int id = tid + it * 256;
            int row = id >> 3, c4 = id & 7;
            const float* g = x + (size_t)(mtile * MT + row) * ROWF
                               + blk * INB + kcol + c4 * 4;
            cp16(sA + row * (PADF * 4) + c4 * 16, g);
        }
        const float* wt = g_wtf32 + (size_t)blk * OUTB * INB;
#pragma unroll
        for (int it = 0; it < 8; it++) {                 // B: 2048 16B chunks
            int id = tid + it * 256;
            int row = id >> 3, c4 = id & 7;
            cp16(sB + row * (PADF * 4) + c4 * 16, wt + row * INB + kcol + c4 * 4);
        }
    };

#pragma unroll
    for (int s = 0; s < NSTAGE; s++) {
        cp_stage(s, s);
        asm volatile("cp.async.commit_group;" ::: "memory");
    }

    float acc[4][4][4];
#pragma unroll
    for (int i = 0; i < 4; i++)
#pragma unroll
        for (int j = 0; j < 4; j++)
#pragma unroll
            for (int r = 0; r < 4; r++) acc[i][j][r] = 0.0f;

    // ldmatrix per-lane base offsets (within a stage)
    // A: tiles (rows r0..+7, k0-3), (r0+8, k0-3), (r0, k4-7), (r0+8, k4-7)
    const uint32_t laneOffA = (uint32_t)(lane & 15) * (PADF * 4) + (uint32_t)(lane >> 4) * 16;
    // B: tiles (n0..+7,k0-3),(n0..+7,k4-7),(n0+8..,k0-3),(n0+8..,k4-7)
    const uint32_t laneOffB = (uint32_t)(wid * 32 + ((lane >> 4) & 1) * 8 + (lane & 7)) * (PADF * 4)
                            + (uint32_t)((lane >> 3) & 1) * 16;

    for (int kc = 0; kc < NCHUNK; kc++) {
        asm volatile("cp.async.wait_group %0;" :: "n"(NSTAGE - 1) : "memory");
        __syncthreads();   // stage kc%2 ready

        const int s = kc & 1;
        const uint32_t stg = sbase + SM_TILES + s * STAGE_BYTES;
        const uint32_t aB = stg + laneOffA;
        const uint32_t bB = stg + A_BYTES + laneOffB;

#pragma unroll
        for (int ks = 0; ks < KC / 8; ks++) {
            uint32_t a[4][4], b[8];
#pragma unroll
            for (int i = 0; i < 4; i++)
                ldsm4(a[i], aB + i * 16 * (PADF * 4) + ks * 32);
            ldsm4(b + 0, bB + ks * 32);                       // j=0,1
            ldsm4(b + 4, bB + 16 * (PADF * 4) + ks * 32);     // j=2,3
#pragma unroll
            for (int i = 0; i < 4; i++)
#pragma unroll
                for (int j = 0; j < 4; j++)
                    mma_tf32(acc[i][j], a[i], b + 2 * j);
        }

        __syncthreads();   // all warps done reading stage s before refill

        if (kc + NSTAGE < NCHUNK) cp_stage(kc + NSTAGE, s);
        asm volatile("cp.async.commit_group;" ::: "memory");  // uniform group count
    }

    // ---- epilogue: bias + store (float2) ----
    const float* bsm = reinterpret_cast<const float*>(smem + SM_BIAS);
#pragma unroll
    for (int i = 0; i < 4; i++) {
        const int row0 = mtile * MT + i * 16 + gID;
#pragma unroll
        for (int j = 0; j < 4; j++) {
            const int colL = wid * 32 + j * 8 + tig * 2;
            const int colG = blk * OUTB + colL;
            float2 v0, v1;
            v0.x = acc[i][j][0] + bsm[colL];
            v0.y = acc[i][j][1] + bsm[colL + 1];
            v1.x = acc[i][j][2] + bsm[colL];
            v1.y = acc[i][j][3] + bsm[colL + 1];
            *reinterpret_cast<float2*>(out + (size_t)row0 * ROWF + colG) = v0;
            *reinterpret_cast<float2*>(out + (size_t)(row0 + 8) * ROWF + colG) = v1;
        }
    }
}

// ---------------- host ----------------

extern "C" void kernel_launch(void* const* d_in, const int* in_sizes, int n_in,
                              void* d_out, int out_size) {
    const float* x    = (const float*)d_in[0];
    const float* w    = (const float*)d_in[1];
    const float* bias = (const float*)d_in[2];
    float* out        = (float*)d_out;

    static bool attr_done = false;
    if (!attr_done) {
        cudaFuncSetAttribute(blocklinear_mma_kernel,
                             cudaFuncAttributeMaxDynamicSharedMemorySize, SMEM_TOTAL);
        attr_done = true;
    }

    // prologue: w -> tf32(rna) in g_wtf32 (16 MB, ~5us)
    round_w_kernel<<<WELEMS / 4 / 256, 256>>>(reinterpret_cast<const float4*>(w));

    dim3 grid(NBLK, BATCHSZ / MT);   // (64, 64)
    blocklinear_mma_kernel<<<grid, 256, SMEM_TOTAL>>>(x, bias, out);
}

// round 14
// speedup vs baseline: 2.1388x; 1.0876x over previous
#include <cuda_runtime.h>
#include <cstdint>

// ----------------------------------------------------------------------------
// BlockLinear via mma.sync tf32 + ldmatrix (compute_103: no tcgen05).
// out[4096, 64*256] = x-blocks @ w-blocks^T + bias
// R12: CTA 128x128 tile, 256 thr (8 warps, 2m x 4n, warp tile 64x32),
// 3-stage cp.async, ONE __syncthreads per chunk, 2-chunk lookahead.
// w pre-rounded to tf32(rna) into __device__ scratch; x HW-truncated.
// Inner loop: 6 ldmatrix.x4 + 16 HMMA per k8-slice (R11-proven mapping).
// ----------------------------------------------------------------------------

#define NBLK    64
#define INB     256
#define OUTB    256
#define BATCHSZ 4096
#define ROWF    (NBLK * INB)          // 16384
#define WELEMS  (NBLK * OUTB * INB)   // 4194304

#define MT      128
#define NT      128
#define KC      32
#define NCHUNK  (INB / KC)      // 8
#define NSTAGE  3

#define PADF    36                        // floats per smem row (144B)
#define A_BYTES (MT * PADF * 4)           // 18432
#define B_BYTES (NT * PADF * 4)           // 18432
#define STAGE_BYTES (A_BYTES + B_BYTES)   // 36864
#define SM_BIAS  0
#define SM_TILES 1024
#define SMEM_TOTAL (SM_TILES + NSTAGE * STAGE_BYTES)   // 111616 -> 2 CTAs/SM

// pre-rounded tf32 weights (static device scratch: no allocation)
__device__ float g_wtf32[WELEMS];

// ---------------- device helpers ----------------

__device__ __forceinline__ uint32_t smem_u32(const void* p) {
    uint32_t a;
    asm("{ .reg .u64 t; cvta.to.shared.u64 t, %1; cvt.u32.u64 %0, t; }" : "=r"(a) : "l"(p));
    return a;
}

__device__ __forceinline__ void cp16(uint32_t dst, const void* src) {
    asm volatile("cp.async.cg.shared.global [%0], [%1], 16;" :: "r"(dst), "l"(src));
}

__device__ __forceinline__ uint32_t f2tf32(float f) {
    uint32_t r;
    asm("cvt.rna.tf32.f32 %0, %1;" : "=r"(r) : "f"(f));
    return r;
}

// ldmatrix x4 b16: moves 4 tiles of 8 rows x 16B; per-lane address = row start.
__device__ __forceinline__ void ldsm4(uint32_t* r, uint32_t addr) {
    asm volatile("ldmatrix.sync.aligned.m8n8.x4.shared.b16 {%0,%1,%2,%3}, [%4];"
                 : "=r"(r[0]), "=r"(r[1]), "=r"(r[2]), "=r"(r[3]) : "r"(addr));
}

__device__ __forceinline__ void mma_tf32(float* c, const uint32_t* a, const uint32_t* b) {
    asm volatile(
        "mma.sync.aligned.m16n8k8.row.col.f32.tf32.tf32.f32 "
        "{%0,%1,%2,%3}, {%4,%5,%6,%7}, {%8,%9}, {%0,%1,%2,%3};"
        : "+f"(c[0]), "+f"(c[1]), "+f"(c[2]), "+f"(c[3])
        : "r"(a[0]), "r"(a[1]), "r"(a[2]), "r"(a[3]), "r"(b[0]), "r"(b[1]));
}

// ---------------- prologue: round w to tf32 (rna) ----------------

__global__ void __launch_bounds__(256)
round_w_kernel(const float4* __restrict__ w) {
    int i = blockIdx.x * blockDim.x + threadIdx.x;
    float4 v = w[i];
    float4 o;
    o.x = __uint_as_float(f2tf32(v.x));
    o.y = __uint_as_float(f2tf32(v.y));
    o.z = __uint_as_float(f2tf32(v.z));
    o.w = __uint_as_float(f2tf32(v.w));
    reinterpret_cast<float4*>(g_wtf32)[i] = o;
}

// ---------------- main kernel ----------------

__global__ void __launch_bounds__(256, 2)
blocklinear_mma_kernel(const float* __restrict__ x,
                       const float* __restrict__ bias,
                       float* __restrict__ out) {
    extern __shared__ char smem[];
    const uint32_t sbase = smem_u32(smem);
    const int tid   = threadIdx.x;
    const int bx    = blockIdx.x;        // 0..127: (blk, n-half)
    const int blk   = bx >> 1;           // weight block
    const int nth   = bx & 1;            // which 128-col half of the block
    const int mtile = blockIdx.y;        // 0..31: 128-row batch slice

    if (tid < NT)
        reinterpret_cast<float*>(smem + SM_BIAS)[tid] = bias[blk * OUTB + nth * NT + tid];

    const int wid  = tid >> 5;
    const int lane = tid & 31;
    const int gID  = lane >> 2;
    const int tig  = lane & 3;
    const int wm   = wid >> 2;           // 0..1 -> 64-row strip
    const int wn   = wid & 3;            // 0..3 -> 32-col strip

    // ---- cp.async stage loader: A [128x32] from x, B [128x32] from g_wtf32 ----
    const float* wt = g_wtf32 + (size_t)blk * OUTB * INB + (size_t)nth * NT * INB;
    auto cp_stage = [&](int kc, int s) {
        const uint32_t sA = sbase + SM_TILES + s * STAGE_BYTES;
        const uint32_t sB = sA + A_BYTES;
        const int kcol = kc * KC;
#pragma unroll
        for (int it = 0; it < 4; it++) {                 // A: 1024 16B chunks
            int id = tid + it * 256;
            int row = id >> 3, c4 = id & 7;
            const float* g = x + (size_t)(mtile * MT + row) * ROWF
                               + blk * INB + kcol + c4 * 4;
            cp16(sA + row * (PADF * 4) + c4 * 16, g);
        }
#pragma unroll
        for (int it = 0; it < 4; it++) {                 // B: 1024 16B chunks
            int id = tid + it * 256;
            int row = id >> 3, c4 = id & 7;
            cp16(sB + row * (PADF * 4) + c4 * 16, wt + row * INB + kcol + c4 * 4);
        }
    };

    // prologue: NSTAGE-1 = 2 chunks in flight
#pragma unroll
    for (int s = 0; s < NSTAGE - 1; s++) {
        cp_stage(s, s);
        asm volatile("cp.async.commit_group;" ::: "memory");
    }

    float acc[4][4][4];
#pragma unroll
    for (int i = 0; i < 4; i++)
#pragma unroll
        for (int j = 0; j < 4; j++)
#pragma unroll
            for (int r = 0; r < 4; r++) acc[i][j][r] = 0.0f;

    // ldmatrix per-lane base offsets (within a stage)
    // A tiles: (m..+7,k0-3),(m+8..,k0-3),(m..,k4-7),(m+8..,k4-7)
    const uint32_t laneOffA = (uint32_t)(wm * 64 + (lane & 15)) * (PADF * 4)
                            + (uint32_t)(lane >> 4) * 16;
    // B tiles: (n..+7,k0-3),(n..+7,k4-7),(n+8..,k0-3),(n+8..,k4-7)
    const uint32_t laneOffB = (uint32_t)(wn * 32 + ((lane >> 4) & 1) * 8 + (lane & 7)) * (PADF * 4)
                            + (uint32_t)((lane >> 3) & 1) * 16;

    for (int kc = 0; kc < NCHUNK; kc++) {
        // chunk kc arrived (committed groups: kc+2; allow 1 pending)
        asm volatile("cp.async.wait_group 1;" ::: "memory");
        __syncthreads();   // also guarantees compute(kc-1) done by ALL warps

        // refill: chunk kc+2 -> slot (kc+2)%3 (held chunk kc-1; safe after barrier)
        if (kc + NSTAGE - 1 < NCHUNK) cp_stage(kc + NSTAGE - 1, (kc + NSTAGE - 1) % NSTAGE);
        asm volatile("cp.async.commit_group;" ::: "memory");   // uniform group count

        const uint32_t stg = sbase + SM_TILES + (kc % NSTAGE) * STAGE_BYTES;
        const uint32_t aB = stg + laneOffA;
        const uint32_t bB = stg + A_BYTES + laneOffB;

#pragma unroll
        for (int ks = 0; ks < KC / 8; ks++) {
            uint32_t a[4][4], b[8];
#pragma unroll
            for (int i = 0; i < 4; i++)
                ldsm4(a[i], aB + i * 16 * (PADF * 4) + ks * 32);
            ldsm4(b + 0, bB + ks * 32);                       // j=0,1
            ldsm4(b + 4, bB + 16 * (PADF * 4) + ks * 32);     // j=2,3
#pragma unroll
            for (int i = 0; i < 4; i++)
#pragma unroll
                for (int j = 0; j < 4; j++)
                    mma_tf32(acc[i][j], a[i], b + 2 * j);
        }
    }

    // ---- epilogue: bias + store (float2) ----
    const float* bsm = reinterpret_cast<const float*>(smem + SM_BIAS);
#pragma unroll
    for (int i = 0; i < 4; i++) {
        const int row0 = mtile * MT + wm * 64 + i * 16 + gID;
#pragma unroll
        for (int j = 0; j < 4; j++) {
            const int colL = wn * 32 + j * 8 + tig * 2;
            const int colG = blk * OUTB + nth * NT + colL;
            float2 v0, v1;
            v0.x = acc[i][j][0] + bsm[colL];
            v0.y = acc[i][j][1] + bsm[colL + 1];
            v1.x = acc[i][j][2] + bsm[colL];
            v1.y = acc[i][j][3] + bsm[colL + 1];
            *reinterpret_cast<float2*>(out + (size_t)row0 * ROWF + colG) = v0;
            *reinterpret_cast<float2*>(out + (size_t)(row0 + 8) * ROWF + colG) = v1;
        }
    }
}

// ---------------- host ----------------

extern "C" void kernel_launch(void* const* d_in, const int* in_sizes, int n_in,
                              void* d_out, int out_size) {
    const float* x    = (const float*)d_in[0];
    const float* w    = (const float*)d_in[1];
    const float* bias = (const float*)d_in[2];
    float* out        = (float*)d_out;

    static bool attr_done = false;
    if (!attr_done) {
        cudaFuncSetAttribute(blocklinear_mma_kernel,
                             cudaFuncAttributeMaxDynamicSharedMemorySize, SMEM_TOTAL);
        attr_done = true;
    }

    // prologue: w -> tf32(rna) in g_wtf32 (16 MB, ~5us)
    round_w_kernel<<<WELEMS / 4 / 256, 256>>>(reinterpret_cast<const float4*>(w));

    dim3 grid(NBLK * 2, BATCHSZ / MT);   // (128, 32): n-halves adjacent -> x L2 dedup
    blocklinear_mma_kernel<<<grid, 256, SMEM_TOTAL>>>(x, bias, out);
}